// round 12
// baseline (speedup 1.0000x reference)
#include <cuda_runtime.h>
#include <cuda_bf16.h>
#include <math.h>
#include <stdint.h>

// Problem constants
#define T_  256
#define B_  64
#define I_  1024
#define L_  2
#define G_  4
#define H_  1024
#define R_  16

#define N_TOT  (G_ * H_)
#define K_HALF 1024

// GEMM config: grid (32 mtiles, 8 k-splits), 256 thr, 2 CTA/SM
#define KS     8
#define KSLICE 256
#define NSTEP  (KSLICE / 16)
#define PF     3

// Scratch (allocation-free; counters monotonic across graph replays)
__device__ float    g_pre[KS * N_TOT * B_];   // [ks][i][g][h32][b]  8 MB
__device__ float    g_u[2 * G_ * R_ * B_];    // [src][g][r][b]
__device__ unsigned g_mcnt[32];
__device__ unsigned g_ucnt;

#define SWZ(o) ((o) ^ (((o) >> 3) & 0x70))

__device__ __forceinline__ uint32_t smem_u32(const void* p) {
    uint32_t a;
    asm("{ .reg .u64 t; cvta.to.shared.u64 t, %1; cvt.u32.u64 %0, t; }" : "=r"(a) : "l"(p));
    return a;
}
__device__ __forceinline__ void cvt_hilo(float a, float b, uint32_t& hi, uint32_t& lo) {
    __nv_bfloat162 h = __floats2bfloat162_rn(a, b);
    float ra = a - __bfloat162float(h.x);
    float rb = b - __bfloat162float(h.y);
    __nv_bfloat162 l = __floats2bfloat162_rn(ra, rb);
    hi = *(uint32_t*)&h;
    lo = *(uint32_t*)&l;
}
__device__ __forceinline__ void ldsm4(uint32_t* r, uint32_t addr) {
    asm volatile("ldmatrix.sync.aligned.m8n8.x4.shared.b16 {%0,%1,%2,%3}, [%4];"
                 : "=r"(r[0]), "=r"(r[1]), "=r"(r[2]), "=r"(r[3]) : "r"(addr));
}
__device__ __forceinline__ void mma_bf16(float* d, const uint32_t* a, uint32_t b0, uint32_t b1) {
    asm volatile("mma.sync.aligned.m16n8k16.row.col.f32.bf16.bf16.f32 "
                 "{%0,%1,%2,%3}, {%4,%5,%6,%7}, {%8,%9}, {%0,%1,%2,%3};"
                 : "+f"(d[0]), "+f"(d[1]), "+f"(d[2]), "+f"(d[3])
                 : "r"(a[0]), "r"(a[1]), "r"(a[2]), "r"(a[3]), "r"(b0), "r"(b1));
}

// ---------------------------------------------------------------------------
// Fully fused kernel: LoRA + HMMA split-K GEMM + last-CTA gates (lean tail).
// mtile i covers h in [32i, 32i+32) for all 4 gates.
// ---------------------------------------------------------------------------
__global__ void __launch_bounds__(256, 2)
fused_kernel(const float* __restrict__ x, const float* __restrict__ h0,
             const float* __restrict__ W_x, const float* __restrict__ W_h,
             const float* __restrict__ A_x, const float* __restrict__ A_h,
             const float* __restrict__ b_x, const float* __restrict__ b_h,
             const float* __restrict__ B_x, const float* __restrict__ B_h,
             const float* __restrict__ c0,  float* __restrict__ out, int l)
{
    // phase-overlaid: [mainloop: x tiles 16KB] [gates: pre 32KB @0, u-slice 8KB @32K]
    __shared__ __align__(1024) uint8_t s_all[40960];
    __shared__ unsigned s_old;

    const int tid  = threadIdx.x;
    const int wid  = tid >> 5;
    const int lane = tid & 31;
    const int ks   = blockIdx.y;
    const int i    = blockIdx.x;

    const float* Wbase;
    const float* vbase;
    int koff;
    if (ks < 4) { Wbase = W_x + (size_t)l * N_TOT * K_HALF; vbase = x;
                  koff = ks * KSLICE; }
    else        { Wbase = W_h + (size_t)l * N_TOT * K_HALF; vbase = h0 + (size_t)l * B_ * H_;
                  koff = (ks - 4) * KSLICE; }

    const int gate = wid >> 1;
    const int hb   = (wid & 1) * 16;
    const int lrow = lane >> 2;
    const int q    = lane & 3;

    const float* WA = Wbase + (size_t)(gate * 1024 + i * 32 + hb + lrow) * K_HALF + koff;
    const float* WB = WA + 8 * (size_t)K_HALF;

    // -------- first PF steps of W loads --------
    float2 wbufA0[PF], wbufA1[PF], wbufB0[PF], wbufB1[PF];
#pragma unroll
    for (int s = 0; s < PF; ++s) {
        const int kk = s * 16 + 2 * q;
        wbufA0[s] = *(const float2*)(WA + kk);
        wbufA1[s] = *(const float2*)(WA + kk + 8);
        wbufB0[s] = *(const float2*)(WB + kk);
        wbufB1[s] = *(const float2*)(WB + kk + 8);
    }

    // -------- LoRA projections --------
    {
        const uint32_t wg = ((uint32_t)blockIdx.y * 32u + blockIdx.x) * 8u + wid;
#pragma unroll
        for (int t = 0; t < 2; ++t) {
            const uint32_t task = wg * 2u + t;
            const int src  = task >> 11;
            const int rem  = task & 2047;
            const int gg   = rem >> 9;
            const int rem2 = rem & 511;
            const int b    = rem2 >> 3;
            const int rp   = rem2 & 7;

            const float* vec = (src == 0) ? (x + (size_t)b * I_)
                                          : (h0 + (size_t)l * B_ * H_ + (size_t)b * H_);
            const float* A = ((src == 0) ? A_x : A_h) + ((size_t)(l * G_ + gg)) * R_ * K_HALF;
            const float4* v4 = (const float4*)vec;
            const float4* a0 = (const float4*)(A + (size_t)(rp * 2) * K_HALF);
            const float4* a1 = (const float4*)(A + (size_t)(rp * 2 + 1) * K_HALF);

            float acc0 = 0.f, acc1 = 0.f;
#pragma unroll
            for (int j = 0; j < 8; ++j) {
                const int i4 = j * 32 + lane;
                float4 v = v4[i4];
                float4 a = a0[i4];
                float4 c = a1[i4];
                acc0 += v.x * a.x + v.y * a.y + v.z * a.z + v.w * a.w;
                acc1 += v.x * c.x + v.y * c.y + v.z * c.z + v.w * c.w;
            }
#pragma unroll
            for (int off = 16; off > 0; off >>= 1) {
                acc0 += __shfl_down_sync(0xffffffffu, acc0, off);
                acc1 += __shfl_down_sync(0xffffffffu, acc1, off);
            }
            if (lane == 0) {
                float* u = &g_u[((size_t)(src * G_ + gg) * R_) * B_ + b];
                u[(size_t)(rp * 2) * B_]     = acc0;
                u[(size_t)(rp * 2 + 1) * B_] = acc1;
            }
        }
        __threadfence();
        __syncthreads();
        if (tid == 0) atomicAdd(&g_ucnt, 1u);
    }

    // -------- x staging geometry --------
    const int xn = tid >> 2;
    const int xq = tid & 3;
    const float* Xsrc = vbase + (size_t)xn * K_HALF + koff + xq * 16;
    uint32_t st_off[4];
#pragma unroll
    for (int j = 0; j < 4; ++j) {
        uint32_t o = (uint32_t)xn * 128u + (uint32_t)xq * 32u + (uint32_t)j * 8u;
        st_off[j] = SWZ(o);
    }

    const int lm_row  = 8 * ((lane >> 4) & 1) + (lane & 7);
    const int lm_kb   = ((lane >> 3) & 1) * 16;
    const int cswz    = (lane & 7) << 4;
    const uint32_t rowoff = (uint32_t)lm_row * 128u;
    const uint32_t hi_base = smem_u32(s_all);
    const uint32_t lo_base = hi_base + 8192;
    uint8_t* sxh = s_all;
    uint8_t* sxl = s_all + 8192;

    float acc[8][4];
#pragma unroll
    for (int t = 0; t < 8; ++t)
#pragma unroll
        for (int j = 0; j < 4; ++j) acc[t][j] = 0.f;

#pragma unroll
    for (int step = 0; step < NSTEP; ++step) {
        if ((step & 3) == 0) {
            if (step) __syncthreads();
            const float4* s4 = (const float4*)(Xsrc + (step >> 2) * 64);
#pragma unroll
            for (int j = 0; j < 4; ++j) {
                float4 f = s4[j];
                uint32_t h01, l01, h23, l23;
                cvt_hilo(f.x, f.y, h01, l01);
                cvt_hilo(f.z, f.w, h23, l23);
                *(uint2*)(sxh + st_off[j]) = make_uint2(h01, h23);
                *(uint2*)(sxl + st_off[j]) = make_uint2(l01, l23);
            }
            __syncthreads();
        }

        const int cur = step % PF;

        uint32_t a_hi[4], a_lo[4];
        cvt_hilo(wbufA0[cur].x, wbufA0[cur].y, a_hi[0], a_lo[0]);
        cvt_hilo(wbufB0[cur].x, wbufB0[cur].y, a_hi[1], a_lo[1]);
        cvt_hilo(wbufA1[cur].x, wbufA1[cur].y, a_hi[2], a_lo[2]);
        cvt_hilo(wbufB1[cur].x, wbufB1[cur].y, a_hi[3], a_lo[3]);

        if (step + PF < NSTEP) {
            const int kk = (step + PF) * 16 + 2 * q;
            wbufA0[cur] = *(const float2*)(WA + kk);
            wbufA1[cur] = *(const float2*)(WA + kk + 8);
            wbufB0[cur] = *(const float2*)(WB + kk);
            wbufB1[cur] = *(const float2*)(WB + kk + 8);
        }

        const int kb = lm_kb + (step & 3) * 32;
        const uint32_t koffsw = (uint32_t)(kb ^ cswz);

#pragma unroll
        for (int tp = 0; tp < 4; ++tp) {
            const uint32_t off = rowoff + (uint32_t)tp * 2048u + koffsw;
            uint32_t bh[4], bl[4];
            ldsm4(bh, hi_base + off);
            ldsm4(bl, lo_base + off);
            mma_bf16(acc[2 * tp],     a_hi, bh[0], bh[1]);
            mma_bf16(acc[2 * tp],     a_hi, bl[0], bl[1]);
            mma_bf16(acc[2 * tp],     a_lo, bh[0], bh[1]);
            mma_bf16(acc[2 * tp + 1], a_hi, bh[2], bh[3]);
            mma_bf16(acc[2 * tp + 1], a_hi, bl[2], bl[3]);
            mma_bf16(acc[2 * tp + 1], a_lo, bh[2], bh[3]);
        }
    }

    // -------- epilogue: store partials [ks][i][g][h32][b] --------
    {
        float* base0 = &g_pre[(((size_t)ks * 32 + i) * 4 + gate) * 2048
                              + (size_t)(hb + lrow) * 64];
        float* base8 = base0 + 8 * 64;
#pragma unroll
        for (int t = 0; t < 8; ++t) {
            *(float2*)(base0 + t * 8 + 2 * q) = make_float2(acc[t][0], acc[t][1]);
            *(float2*)(base8 + t * 8 + 2 * q) = make_float2(acc[t][2], acc[t][3]);
        }
    }

    // -------- last-CTA election --------
    __threadfence();
    __syncthreads();
    if (tid == 0) s_old = atomicAdd(&g_mcnt[i], 1u);
    __syncthreads();
    if ((s_old & 7u) != 7u) return;

    // ======================= GATES PHASE (lean registers) ===================
    if (tid == 0) {
        const unsigned tgt = ((s_old >> 3) + 1u) * 256u;   // all LoRA done
        while (*((volatile unsigned*)&g_ucnt) < tgt) __nanosleep(64);
    }
    __syncthreads();
    __threadfence();

    float* spre = (float*)s_all;                 // [4][32][64]  32 KB
    float* su   = (float*)(s_all + 32768);       // [2][16][64]   8 KB

    const int hh = tid >> 3;          // 0..31
    const int bo = (tid & 7) * 8;     // 0..56
    const int hg = i * 32 + hh;

#pragma unroll 1
    for (int g = 0; g < 4; ++g) {
        // stage u[src][g] slice (8 KB, coalesced)
        {
            const float4* s0 = (const float4*)(g_u + ((size_t)(0 * G_ + g) * R_) * B_);
            const float4* s1 = (const float4*)(g_u + ((size_t)(1 * G_ + g) * R_) * B_);
            float4* d = (float4*)su;
            d[tid]       = s0[tid];
            d[256 + tid] = s1[tid];
        }
        __syncthreads();

        float a[8];
        {
            const float bias = b_x[(l * G_ + g) * H_ + hg] + b_h[(l * G_ + g) * H_ + hg];
#pragma unroll
            for (int k = 0; k < 8; ++k) a[k] = bias;
        }

        // split-K partials (L2-hot, coalesced float4)
#pragma unroll
        for (int kss = 0; kss < KS; ++kss) {
            const float* P = g_pre + (((size_t)kss * 32 + i) * 4 + g) * 2048
                             + (size_t)hh * 64 + bo;
            float4 p0 = *(const float4*)P;
            float4 p1 = *(const float4*)(P + 4);
            a[0] += p0.x; a[1] += p0.y; a[2] += p0.z; a[3] += p0.w;
            a[4] += p1.x; a[5] += p1.y; a[6] += p1.z; a[7] += p1.w;
        }

        // LoRA contraction: one B-row float4 at a time (low register pressure)
        const float4* Cx = (const float4*)(B_x + ((size_t)((l * G_ + g) * H_) + hg) * R_);
        const float4* Ch = (const float4*)(B_h + ((size_t)((l * G_ + g) * H_) + hg) * R_);
#pragma unroll
        for (int j = 0; j < 4; ++j) {
            const float4 cx = Cx[j];
            const float4 ch = Ch[j];
            const float* ux = su + (j * 4) * 64 + bo;
            const float* uh = su + 1024 + (j * 4) * 64 + bo;
#pragma unroll
            for (int rr = 0; rr < 4; ++rr) {
                const float cxe = (&cx.x)[rr];
                const float che = (&ch.x)[rr];
                float4 u0 = *(const float4*)(ux + rr * 64);
                float4 u1 = *(const float4*)(ux + rr * 64 + 4);
                float4 v0 = *(const float4*)(uh + rr * 64);
                float4 v1 = *(const float4*)(uh + rr * 64 + 4);
                a[0] += cxe * u0.x + che * v0.x;
                a[1] += cxe * u0.y + che * v0.y;
                a[2] += cxe * u0.z + che * v0.z;
                a[3] += cxe * u0.w + che * v0.w;
                a[4] += cxe * u1.x + che * v1.x;
                a[5] += cxe * u1.y + che * v1.y;
                a[6] += cxe * u1.z + che * v1.z;
                a[7] += cxe * u1.w + che * v1.w;
            }
        }

        *(float4*)(spre + ((size_t)g * 32 + hh) * 64 + bo)     = make_float4(a[0], a[1], a[2], a[3]);
        *(float4*)(spre + ((size_t)g * 32 + hh) * 64 + bo + 4) = make_float4(a[4], a[5], a[6], a[7]);
        __syncthreads();   // pre writes done / su free for next g
    }

    // ---- activation + coalesced output: thread = (b = tid>>2, 8 h) ----
    {
        const int b  = tid >> 2;
        const int h8 = (tid & 3) * 8;
        const float* c0p = c0 + (size_t)l * B_ * H_ + (size_t)b * H_ + i * 32 + h8;
        float4 cva = *(const float4*)c0p;
        float4 cvb = *(const float4*)(c0p + 4);
        float hn[8], cn[8];
#pragma unroll
        for (int k = 0; k < 8; ++k) {
            const int hx = h8 + k;
            const float pi = spre[(0 * 32 + hx) * 64 + b];
            const float pf = spre[(1 * 32 + hx) * 64 + b];
            const float pg = spre[(2 * 32 + hx) * 64 + b];
            const float po = spre[(3 * 32 + hx) * 64 + b];
            const float i_t = 1.f / (1.f + expf(-pi));
            const float f_t = 1.f / (1.f + expf(-pf));
            const float g_t = tanhf(pg);
            const float o_t = 1.f / (1.f + expf(-po));
            const float cin = (k < 4) ? (&cva.x)[k] : (&cvb.x)[k - 4];
            cn[k] = f_t * cin + i_t * g_t;
            hn[k] = o_t * tanhf(cn[k]);
        }
        const size_t idx = (size_t)b * H_ + i * 32 + h8;
        *(float4*)&out[(size_t)B_ * H_ * (1 + l) + idx]     = make_float4(hn[0], hn[1], hn[2], hn[3]);
        *(float4*)&out[(size_t)B_ * H_ * (1 + l) + idx + 4] = make_float4(hn[4], hn[5], hn[6], hn[7]);
        *(float4*)&out[(size_t)B_ * H_ * (3 + l) + idx]     = make_float4(cn[0], cn[1], cn[2], cn[3]);
        *(float4*)&out[(size_t)B_ * H_ * (3 + l) + idx + 4] = make_float4(cn[4], cn[5], cn[6], cn[7]);
        if (l == 1) {
            *(float4*)&out[idx]     = make_float4(hn[0], hn[1], hn[2], hn[3]);
            *(float4*)&out[idx + 4] = make_float4(hn[4], hn[5], hn[6], hn[7]);
        }
    }
}

// ---------------------------------------------------------------------------
extern "C" void kernel_launch(void* const* d_in, const int* in_sizes, int n_in,
                              void* d_out, int out_size)
{
    const float* input_seq = (const float*)d_in[0];
    const float* h0        = (const float*)d_in[1];
    const float* c0        = (const float*)d_in[2];
    const float* W_x       = (const float*)d_in[3];
    const float* W_h       = (const float*)d_in[4];
    const float* b_x       = (const float*)d_in[5];
    const float* b_h       = (const float*)d_in[6];
    const float* A_x       = (const float*)d_in[7];
    const float* B_x       = (const float*)d_in[8];
    const float* A_h       = (const float*)d_in[9];
    const float* B_h       = (const float*)d_in[10];
    float* out = (float*)d_out;

    const float* x_last = input_seq + (size_t)(T_ - 1) * B_ * I_;

    for (int l = 0; l < L_; ++l) {
        const float* x = (l == 0) ? x_last : (out + (size_t)B_ * H_);  // h_t[0]
        fused_kernel<<<dim3(32, KS), 256>>>(x, h0, W_x, W_h, A_x, A_h,
                                            b_x, b_h, B_x, B_h, c0, out, l);
    }
}

// round 13
// speedup vs baseline: 1.6408x; 1.6408x over previous
#include <cuda_runtime.h>
#include <cuda_fp16.h>
#include <math.h>
#include <stdint.h>

// Problem constants
#define T_  256
#define B_  64
#define I_  1024
#define L_  2
#define G_  4
#define H_  1024
#define R_  16

#define N_TOT  (G_ * H_)
#define K_HALF 1024

// GEMM config: grid (32 M-tiles, 8 k-splits), 256 thr, 2 CTA/SM
#define KS     8
#define KSLICE 256             // K per split
#define MT     128             // M rows per CTA
#define NSTEP  (KSLICE / 16)   // 16 k16 steps
#define PF     3               // W prefetch depth (validated)

// Scratch
__device__ float g_pre[KS * N_TOT * B_];   // [ks][m][b]  8 MB
__device__ float g_u[2 * G_ * R_ * B_];    // [src][g][r][b]  (b fast)

#define SWZ(o) ((o) ^ (((o) >> 3) & 0x70))

__device__ __forceinline__ uint32_t smem_u32(const void* p) {
    uint32_t a;
    asm("{ .reg .u64 t; cvta.to.shared.u64 t, %1; cvt.u32.u64 %0, t; }" : "=r"(a) : "l"(p));
    return a;
}
__device__ __forceinline__ uint32_t pack_h2(float a, float b) {
    __half2 h = __floats2half2_rn(a, b);
    return *(uint32_t*)&h;
}
__device__ __forceinline__ void ldsm4(uint32_t* r, uint32_t addr) {
    asm volatile("ldmatrix.sync.aligned.m8n8.x4.shared.b16 {%0,%1,%2,%3}, [%4];"
                 : "=r"(r[0]), "=r"(r[1]), "=r"(r[2]), "=r"(r[3]) : "r"(addr));
}
__device__ __forceinline__ void mma_fp16(float* d, const uint32_t* a, uint32_t b0, uint32_t b1) {
    asm volatile("mma.sync.aligned.m16n8k16.row.col.f32.f16.f16.f32 "
                 "{%0,%1,%2,%3}, {%4,%5,%6,%7}, {%8,%9}, {%0,%1,%2,%3};"
                 : "+f"(d[0]), "+f"(d[1]), "+f"(d[2]), "+f"(d[3])
                 : "r"(a[0]), "r"(a[1]), "r"(a[2]), "r"(a[3]), "r"(b0), "r"(b1));
}

// ---------------------------------------------------------------------------
// Fused kernel: (a) rank-16 LoRA projections in fp32 (hidden under the W
// stream), (b) HMMA split-K GEMM, single-pass fp16, fp32 accumulate.
// ---------------------------------------------------------------------------
__global__ void __launch_bounds__(256, 2)
gemm_mma_kernel(const float* __restrict__ x, const float* __restrict__ h0,
                const float* __restrict__ W_x, const float* __restrict__ W_h,
                const float* __restrict__ A_x, const float* __restrict__ A_h,
                int l)
{
    __shared__ __align__(1024) uint8_t sx_hi[8192];   // x chunk: 64 n x 64 k fp16, SWZ

    const int tid  = threadIdx.x;
    const int wid  = tid >> 5;
    const int lane = tid & 31;
    const int ks   = blockIdx.y;
    const int m0   = blockIdx.x * MT;

    const float* Wbase;
    const float* vbase;
    int koff;
    if (ks < 4) { Wbase = W_x + (size_t)l * N_TOT * K_HALF; vbase = x;
                  koff = ks * KSLICE; }
    else        { Wbase = W_h + (size_t)l * N_TOT * K_HALF; vbase = h0 + (size_t)l * B_ * H_;
                  koff = (ks - 4) * KSLICE; }

    const int g = lane >> 2;
    const int q = lane & 3;

    const float* WA = Wbase + (size_t)(m0 + wid * 16 + g) * K_HALF + koff;
    const float* WB = WA + 8 * (size_t)K_HALF;

    // -------- issue first PF steps of W loads immediately --------
    float2 wbufA0[PF], wbufA1[PF], wbufB0[PF], wbufB1[PF];
#pragma unroll
    for (int s = 0; s < PF; ++s) {
        const int kk = s * 16 + 2 * q;
        wbufA0[s] = *(const float2*)(WA + kk);
        wbufA1[s] = *(const float2*)(WA + kk + 8);
        wbufB0[s] = *(const float2*)(WB + kk);
        wbufB1[s] = *(const float2*)(WB + kk + 8);
    }

    // -------- LoRA projections (fp32 exact; while W loads are in flight) ----
    {
        const uint32_t wg = ((uint32_t)blockIdx.y * 32u + blockIdx.x) * 8u + wid;
#pragma unroll
        for (int t = 0; t < 2; ++t) {
            const uint32_t task = wg * 2u + t;      // 0..4095
            const int src  = task >> 11;
            const int rem  = task & 2047;
            const int gg   = rem >> 9;
            const int rem2 = rem & 511;
            const int b    = rem2 >> 3;
            const int rp   = rem2 & 7;

            const float* vec = (src == 0) ? (x + (size_t)b * I_)
                                          : (h0 + (size_t)l * B_ * H_ + (size_t)b * H_);
            const float* A = ((src == 0) ? A_x : A_h) + ((size_t)(l * G_ + gg)) * R_ * K_HALF;
            const float4* v4 = (const float4*)vec;
            const float4* a0 = (const float4*)(A + (size_t)(rp * 2) * K_HALF);
            const float4* a1 = (const float4*)(A + (size_t)(rp * 2 + 1) * K_HALF);

            float acc0 = 0.f, acc1 = 0.f;
#pragma unroll
            for (int j = 0; j < 8; ++j) {
                const int i4 = j * 32 + lane;
                float4 v = v4[i4];
                float4 a = a0[i4];
                float4 c = a1[i4];
                acc0 += v.x * a.x + v.y * a.y + v.z * a.z + v.w * a.w;
                acc1 += v.x * c.x + v.y * c.y + v.z * c.z + v.w * c.w;
            }
#pragma unroll
            for (int off = 16; off > 0; off >>= 1) {
                acc0 += __shfl_down_sync(0xffffffffu, acc0, off);
                acc1 += __shfl_down_sync(0xffffffffu, acc1, off);
            }
            if (lane == 0) {
                float* u = &g_u[((size_t)(src * G_ + gg) * R_) * B_ + b];
                u[(size_t)(rp * 2) * B_]     = acc0;
                u[(size_t)(rp * 2 + 1) * B_] = acc1;
            }
        }
    }

    // -------- x staging geometry --------
    const int xn = tid >> 2;
    const int xq = tid & 3;
    const float* Xsrc = vbase + (size_t)xn * K_HALF + koff + xq * 16;
    uint32_t st_off[4];
#pragma unroll
    for (int j = 0; j < 4; ++j) {
        uint32_t o = (uint32_t)xn * 128u + (uint32_t)xq * 32u + (uint32_t)j * 8u;
        st_off[j] = SWZ(o);
    }

    // ldmatrix lane geometry
    const int lm_row  = 8 * ((lane >> 4) & 1) + (lane & 7);
    const int lm_kb   = ((lane >> 3) & 1) * 16;
    const int cswz    = (lane & 7) << 4;
    const uint32_t rowoff = (uint32_t)lm_row * 128u;
    const uint32_t hi_base = smem_u32(sx_hi);

    float acc[8][4];
#pragma unroll
    for (int t = 0; t < 8; ++t)
#pragma unroll
        for (int j = 0; j < 4; ++j) acc[t][j] = 0.f;

#pragma unroll
    for (int step = 0; step < NSTEP; ++step) {
        if ((step & 3) == 0) {                 // stage next 64-k chunk of x
            if (step) __syncthreads();
            const float4* s4 = (const float4*)(Xsrc + (step >> 2) * 64);
#pragma unroll
            for (int j = 0; j < 4; ++j) {
                float4 f = s4[j];
                *(uint2*)(sx_hi + st_off[j]) =
                    make_uint2(pack_h2(f.x, f.y), pack_h2(f.z, f.w));
            }
            __syncthreads();
        }

        const int cur = step % PF;             // static under full unroll

        uint32_t a_f[4];
        a_f[0] = pack_h2(wbufA0[cur].x, wbufA0[cur].y);
        a_f[1] = pack_h2(wbufB0[cur].x, wbufB0[cur].y);
        a_f[2] = pack_h2(wbufA1[cur].x, wbufA1[cur].y);
        a_f[3] = pack_h2(wbufB1[cur].x, wbufB1[cur].y);

        if (step + PF < NSTEP) {               // refill the freed slot
            const int kk = (step + PF) * 16 + 2 * q;
            wbufA0[cur] = *(const float2*)(WA + kk);
            wbufA1[cur] = *(const float2*)(WA + kk + 8);
            wbufB0[cur] = *(const float2*)(WB + kk);
            wbufB1[cur] = *(const float2*)(WB + kk + 8);
        }

        const int kb = lm_kb + (step & 3) * 32;
        const uint32_t koffsw = (uint32_t)(kb ^ cswz);

#pragma unroll
        for (int tp = 0; tp < 4; ++tp) {
            const uint32_t off = rowoff + (uint32_t)tp * 2048u + koffsw;
            uint32_t bh[4];
            ldsm4(bh, hi_base + off);
            mma_fp16(acc[2 * tp],     a_f, bh[0], bh[1]);
            mma_fp16(acc[2 * tp + 1], a_f, bh[2], bh[3]);
        }
    }

    // epilogue
    float* base0 = &g_pre[((size_t)ks * N_TOT + m0 + wid * 16 + g) * B_];
    float* base8 = base0 + 8 * B_;
#pragma unroll
    for (int t = 0; t < 8; ++t) {
        *(float2*)(base0 + t * 8 + 2 * q) = make_float2(acc[t][0], acc[t][1]);
        *(float2*)(base8 + t * 8 + 2 * q) = make_float2(acc[t][2], acc[t][3]);
    }
}

// ---------------------------------------------------------------------------
// Gates (R8-validated): one block per TWO h values (grid 512). Thread =
// (gate, b); g_u reused for both h; smem exchange; 128-thread tail.
// ---------------------------------------------------------------------------
__global__ void __launch_bounds__(256)
gates_kernel(const float* __restrict__ b_x,
             const float* __restrict__ b_h,
             const float* __restrict__ B_x,
             const float* __restrict__ B_h,
             const float* __restrict__ c0,
             float* __restrict__ out,
             int l)
{
    __shared__ float sp[G_][2][B_];

    const int h0 = blockIdx.x * 2;
    const int gg = threadIdx.x >> 6;
    const int b  = threadIdx.x & 63;

    float s0 = b_x[(l * G_ + gg) * H_ + h0]     + b_h[(l * G_ + gg) * H_ + h0];
    float s1 = b_x[(l * G_ + gg) * H_ + h0 + 1] + b_h[(l * G_ + gg) * H_ + h0 + 1];

    const float* p = &g_pre[((size_t)gg * H_ + h0) * B_ + b];
#pragma unroll
    for (int ks = 0; ks < KS; ++ks) {
        s0 += p[(size_t)ks * N_TOT * B_];
        s1 += p[(size_t)ks * N_TOT * B_ + B_];
    }

    const float* Bx0 = B_x + ((size_t)((l * G_ + gg) * H_) + h0) * R_;
    const float* Bh0 = B_h + ((size_t)((l * G_ + gg) * H_) + h0) * R_;
    const float* ux = g_u + ((size_t)(0 * G_ + gg) * R_) * B_ + b;
    const float* uh = g_u + ((size_t)(1 * G_ + gg) * R_) * B_ + b;
#pragma unroll
    for (int r = 0; r < R_; ++r) {
        const float u = ux[(size_t)r * B_];
        s0 += Bx0[r] * u;
        s1 += Bx0[R_ + r] * u;
    }
#pragma unroll
    for (int r = 0; r < R_; ++r) {
        const float u = uh[(size_t)r * B_];
        s0 += Bh0[r] * u;
        s1 += Bh0[R_ + r] * u;
    }

    sp[gg][0][b] = s0;
    sp[gg][1][b] = s1;
    __syncthreads();

    if (threadIdx.x < 128) {
        const int bb = threadIdx.x & 63;
        const int hh = threadIdx.x >> 6;
        const int h  = h0 + hh;

        const float i_t = 1.f / (1.f + expf(-sp[0][hh][bb]));
        const float f_t = 1.f / (1.f + expf(-sp[1][hh][bb]));
        const float g_t = tanhf(sp[2][hh][bb]);
        const float o_t = 1.f / (1.f + expf(-sp[3][hh][bb]));

        const float cv   = c0[(size_t)l * B_ * H_ + (size_t)bb * H_ + h];
        const float cnew = f_t * cv + i_t * g_t;
        const float hnew = o_t * tanhf(cnew);

        const size_t idx = (size_t)bb * H_ + h;
        out[(size_t)B_ * H_ * (1 + l) + idx] = hnew;   // h_t[l]
        out[(size_t)B_ * H_ * (3 + l) + idx] = cnew;   // c_t[l]
        if (l == 1)
            out[idx] = hnew;                           // out == h_t[1]
    }
}

// ---------------------------------------------------------------------------
extern "C" void kernel_launch(void* const* d_in, const int* in_sizes, int n_in,
                              void* d_out, int out_size)
{
    const float* input_seq = (const float*)d_in[0];
    const float* h0        = (const float*)d_in[1];
    const float* c0        = (const float*)d_in[2];
    const float* W_x       = (const float*)d_in[3];
    const float* W_h       = (const float*)d_in[4];
    const float* b_x       = (const float*)d_in[5];
    const float* b_h       = (const float*)d_in[6];
    const float* A_x       = (const float*)d_in[7];
    const float* B_x       = (const float*)d_in[8];
    const float* A_h       = (const float*)d_in[9];
    const float* B_h       = (const float*)d_in[10];
    float* out = (float*)d_out;

    const float* x_last = input_seq + (size_t)(T_ - 1) * B_ * I_;

    for (int l = 0; l < L_; ++l) {
        const float* x = (l == 0) ? x_last : (out + (size_t)B_ * H_);  // h_t[0]

        gemm_mma_kernel<<<dim3(N_TOT / MT, KS), 256>>>(x, h0, W_x, W_h, A_x, A_h, l);
        gates_kernel<<<H_ / 2, 256>>>(b_x, b_h, B_x, B_h, c0, out, l);
    }
}